// round 2
// baseline (speedup 1.0000x reference)
#include <cuda_runtime.h>
#include <cstdint>

#define NB 64
#define NT 2048
#define ND 64
#define FDIM 256               // 4*D

// Output section offsets (elements) in the concatenated flat output:
// features [B,T,256] | times [B,T] | delta [B,T,256] | mask [B,T,256]
#define FEAT_OFF   ((size_t)0)
#define TIMES_OFF  ((size_t)NB * NT * FDIM)                       // 33554432
#define DELTA_OFF  (TIMES_OFF + (size_t)NB * NT)                  // 33685504
#define MASK_OFF   (DELTA_OFF + (size_t)NB * NT * FDIM)           // 67239936

// Scratch for the beta recurrence results: [4][B][T] = 2 MB
__device__ float g_beta[4 * NB * NT];

// ---------------------------------------------------------------------------
// Kernel A: parallel linear-recurrence scan.
// beta[0] = 0; beta[i] = a_i * beta[i-1] + c_i  for i >= 1, where
//   a_i = mask(feat[i-1]) * pad_i,  c_i = (t[i]-t[i-1]) * pad_i,
//   pad_i = (t[i] != -1), mask(v) = (v != -1 && v != 0).
// One block per (f, b): 256 blocks x 256 threads, 8 elems/thread.
// ---------------------------------------------------------------------------
__global__ __launch_bounds__(256) void beta_scan_kernel(
    const int* __restrict__ cat1, const int* __restrict__ cat2,
    const float* __restrict__ num1, const float* __restrict__ num2,
    const float* __restrict__ times)
{
    const int f = blockIdx.x & 3;
    const int b = blockIdx.x >> 2;
    const int tid = threadIdx.x;
    const int t0 = tid * 8;

    const float* tp = times + (size_t)b * NT;
    const size_t base = (size_t)b * NT;

    float a[8], c[8];
    float A = 1.0f, C = 0.0f;
    float prev_time = (t0 > 0) ? tp[t0 - 1] : 0.0f;

#pragma unroll
    for (int k = 0; k < 8; k++) {
        const int i = t0 + k;
        const float ti = tp[i];
        if (i == 0) {
            a[k] = 0.0f; c[k] = 0.0f;   // beta[0] = 0: maps any state to 0
        } else {
            float fv;
            const size_t idx = base + (size_t)(i - 1);
            if      (f == 0) fv = (float)cat1[idx];
            else if (f == 1) fv = (float)cat2[idx];
            else if (f == 2) fv = num1[idx];
            else             fv = num2[idx];
            const float m = (fv != -1.0f && fv != 0.0f) ? 1.0f : 0.0f;
            const float p = (ti != -1.0f) ? 1.0f : 0.0f;
            a[k] = m * p;
            c[k] = (ti - prev_time) * p;
        }
        prev_time = ti;
        // compose: new = m_k o old
        C = a[k] * C + c[k];
        A = a[k] * A;
    }

    __shared__ float sA[256];
    __shared__ float sC[256];
    sA[tid] = A; sC[tid] = C;
    __syncthreads();

    // Hillis-Steele inclusive scan of transforms (prev applied first)
#pragma unroll
    for (int off = 1; off < 256; off <<= 1) {
        float pa = 1.0f, pc = 0.0f;
        const float ca = sA[tid], cc = sC[tid];
        const bool has = (tid >= off);
        if (has) { pa = sA[tid - off]; pc = sC[tid - off]; }
        __syncthreads();
        if (has) { sA[tid] = ca * pa; sC[tid] = ca * pc + cc; }
        __syncthreads();
    }

    // state entering this thread's segment = inclusive[tid-1] applied to 0
    float state = (tid > 0) ? sC[tid - 1] : 0.0f;

    float* out = g_beta + ((size_t)f * NB + b) * NT;
#pragma unroll
    for (int k = 0; k < 8; k++) {
        state = a[k] * state + c[k];
        out[t0 + k] = state;
    }
}

// ---------------------------------------------------------------------------
// Kernel B: one warp per (b,t) position. Writes all 4 output sections with
// float4 stores. Embedding gathers hit L2 (tables = 51 MB < 126 MB L2).
// ---------------------------------------------------------------------------
__global__ __launch_bounds__(256) void output_kernel(
    const int* __restrict__ cat1, const int* __restrict__ cat2,
    const float* __restrict__ num1, const float* __restrict__ num2,
    const float* __restrict__ times,
    const float* __restrict__ E1, const float* __restrict__ E2,
    const float* __restrict__ w1, const float* __restrict__ b1,
    const float* __restrict__ w2, const float* __restrict__ b2,
    float* __restrict__ out)
{
    const size_t warp = ((size_t)blockIdx.x * blockDim.x + threadIdx.x) >> 5;
    const int lane = threadIdx.x & 31;
    if (warp >= (size_t)NB * NT) return;
    const size_t p = warp;

    const int   c1 = cat1[p];
    const int   c2 = cat2[p];
    const float n1 = num1[p];
    const float n2 = num2[p];
    const float tv = times[p];

    // ---- features [p*256 .. p*256+255] ----
    float4* fo = (float4*)(out + FEAT_OFF + p * FDIM);
    const float4* e1row = (const float4*)(E1 + (size_t)c1 * ND);
    const float4* e2row = (const float4*)(E2 + (size_t)c2 * ND);
#pragma unroll
    for (int rep = 0; rep < 2; rep++) {
        const int j = lane + rep * 32;          // float4 chunk index 0..63
        float4 v;
        if (j < 16) {
            v = e1row[j];
        } else if (j < 32) {
            v = e2row[j - 16];
        } else if (j < 48) {
            const float4 wv = ((const float4*)w1)[j - 32];
            const float4 bv = ((const float4*)b1)[j - 32];
            v = make_float4(fmaf(n1, wv.x, bv.x), fmaf(n1, wv.y, bv.y),
                            fmaf(n1, wv.z, bv.z), fmaf(n1, wv.w, bv.w));
        } else {
            const float4 wv = ((const float4*)w2)[j - 48];
            const float4 bv = ((const float4*)b2)[j - 48];
            v = make_float4(fmaf(n2, wv.x, bv.x), fmaf(n2, wv.y, bv.y),
                            fmaf(n2, wv.z, bv.z), fmaf(n2, wv.w, bv.w));
        }
        fo[j] = v;
    }

    // ---- times ----
    if (lane == 0) out[TIMES_OFF + p] = tv;

    // ---- delta: beta[f][b][t] broadcast across D ----
    float4* dout = (float4*)(out + DELTA_OFF + p * FDIM);
#pragma unroll
    for (int rep = 0; rep < 2; rep++) {
        const int j = lane + rep * 32;
        const int f = j >> 4;                   // 16 chunks per feature
        const float bv = g_beta[(size_t)f * (NB * NT) + p];
        dout[j] = make_float4(bv, bv, bv, bv);
    }

    // ---- mask: (v != -1 && v != 0) broadcast across D ----
    float m[4];
    m[0] = (c1 != -1 && c1 != 0) ? 1.0f : 0.0f;
    m[1] = (c2 != -1 && c2 != 0) ? 1.0f : 0.0f;
    m[2] = (n1 != -1.0f && n1 != 0.0f) ? 1.0f : 0.0f;
    m[3] = (n2 != -1.0f && n2 != 0.0f) ? 1.0f : 0.0f;
    float4* mo = (float4*)(out + MASK_OFF + p * FDIM);
#pragma unroll
    for (int rep = 0; rep < 2; rep++) {
        const int j = lane + rep * 32;
        const float mv = m[j >> 4];
        mo[j] = make_float4(mv, mv, mv, mv);
    }
}

extern "C" void kernel_launch(void* const* d_in, const int* in_sizes, int n_in,
                              void* d_out, int out_size)
{
    const int*   cat1 = (const int*)d_in[0];
    const int*   cat2 = (const int*)d_in[1];
    const float* num1 = (const float*)d_in[2];
    const float* num2 = (const float*)d_in[3];
    const float* evt  = (const float*)d_in[4];
    const float* E1   = (const float*)d_in[5];
    const float* E2   = (const float*)d_in[6];
    const float* w1   = (const float*)d_in[7];
    const float* b1   = (const float*)d_in[8];
    const float* w2   = (const float*)d_in[9];
    const float* b2   = (const float*)d_in[10];
    float* out = (float*)d_out;

    // Kernel A: 4 features * 64 batches = 256 blocks
    beta_scan_kernel<<<4 * NB, 256>>>(cat1, cat2, num1, num2, evt);

    // Kernel B: one warp per (b,t): 64*2048 = 131072 warps -> 16384 blocks
    const size_t npos = (size_t)NB * NT;
    const int blocks = (int)((npos * 32 + 255) / 256);
    output_kernel<<<blocks, 256>>>(cat1, cat2, num1, num2, evt,
                                   E1, E2, w1, b1, w2, b2, out);
}